// round 12
// baseline (speedup 1.0000x reference)
#include <cuda_runtime.h>
#include <cuda_bf16.h>
#include <cstdint>

#define B_   16
#define N_   2048
#define F_   128
#define HID_ 32
#define FC_  512
#define C_   10

#define BM   128
#define BK   32
#define MB_  (N_ / BM)     // 16
#define NKT  (N_ / BK)     // 64

// ---- xw kernel (tf32 mma.sync, R8-proven) ----
#define XS_  4
#define XNKT (F_ / BK)     // 4
#define ASTR 36
#define BSTR 40
#define APITCH (BM * ASTR)
#define BPITCH (BK * BSTR)
#define XW_SMEM ((XS_ * APITCH + XS_ * BPITCH) * 4)

// ---- main kernel (bf16 mma.sync) ----
#define MSTR 40            // bf16 elements per smem row (80 B) -> frag banks {20g+t} conflict-free
#define A_ELEMS (BM * MSTR)    // per stage
#define B_ELEMS (HID_ * MSTR)  // per stage

// Scratch (no cudaMalloc allowed)
__device__ __align__(16) __nv_bfloat16 g_XWt[B_ * HID_ * N_];  // (X@W1)^T bf16 [B][32][2048]
__device__ float g_part[B_ * MB_ * HID_];                      // per-block relu column sums

// ---------------- helpers ----------------
__device__ __forceinline__ void cp16(void* dst, const void* src) {
    unsigned s = (unsigned)__cvta_generic_to_shared(dst);
    asm volatile("cp.async.cg.shared.global [%0], [%1], 16;" :: "r"(s), "l"(src));
}
__device__ __forceinline__ void cp_commit() { asm volatile("cp.async.commit_group;"); }
template <int NN>
__device__ __forceinline__ void cp_wait() { asm volatile("cp.async.wait_group %0;" :: "n"(NN)); }

__device__ __forceinline__ void mma_tf32(float c[4], float a0, float a1, float a2, float a3,
                                         float b0, float b1) {
    asm volatile(
        "mma.sync.aligned.m16n8k8.row.col.f32.tf32.tf32.f32 "
        "{%0,%1,%2,%3}, {%4,%5,%6,%7}, {%8,%9}, {%0,%1,%2,%3};"
        : "+f"(c[0]), "+f"(c[1]), "+f"(c[2]), "+f"(c[3])
        : "r"(__float_as_uint(a0)), "r"(__float_as_uint(a1)),
          "r"(__float_as_uint(a2)), "r"(__float_as_uint(a3)),
          "r"(__float_as_uint(b0)), "r"(__float_as_uint(b1)));
}
__device__ __forceinline__ void mma_bf16(float c[4], uint32_t a0, uint32_t a1, uint32_t a2,
                                         uint32_t a3, uint32_t b0, uint32_t b1) {
    asm volatile(
        "mma.sync.aligned.m16n8k16.row.col.f32.bf16.bf16.f32 "
        "{%0,%1,%2,%3}, {%4,%5,%6,%7}, {%8,%9}, {%0,%1,%2,%3};"
        : "+f"(c[0]), "+f"(c[1]), "+f"(c[2]), "+f"(c[3])
        : "r"(a0), "r"(a1), "r"(a2), "r"(a3), "r"(b0), "r"(b1));
}
__device__ __forceinline__ uint32_t packbf(float a, float b) {
    __nv_bfloat162 h = __floats2bfloat162_rn(a, b);
    return *reinterpret_cast<uint32_t*>(&h);
}
__device__ __forceinline__ uint32_t lds32(const __nv_bfloat16* p) {
    return *reinterpret_cast<const uint32_t*>(p);
}

// ---------------------------------------------------------------------------
// Kernel 1: XW^T = (X @ W1)^T -> g_XWt (bf16), tf32 mma.sync path.
// grid (MB_, B_), 256 threads.
// ---------------------------------------------------------------------------
__global__ __launch_bounds__(256) void xw_kernel(const float* __restrict__ Xg,
                                                 const float* __restrict__ W1) {
    extern __shared__ __align__(16) float smem[];
    float* As = smem;
    float* Bs = smem + XS_ * APITCH;

    const int tid = threadIdx.x;
    const int b = blockIdx.y;
    const int mb = blockIdx.x;
    const int w = tid >> 5;
    const int lane = tid & 31;
    const int g = lane >> 2;
    const int t = lane & 3;

    const float* Ab = Xg + ((size_t)b * N_ + (size_t)mb * BM) * F_;

    float acc[4][4];
#pragma unroll
    for (int nt = 0; nt < 4; nt++)
#pragma unroll
        for (int i = 0; i < 4; i++) acc[nt][i] = 0.f;

    auto stage = [&](int kt, int p) {
        const int k0s = kt * BK;
#pragma unroll
        for (int i = 0; i < 4; i++) {
            int c = tid + i * 256;
            int row = c >> 3, kq = c & 7;
            cp16(&As[p * APITCH + row * ASTR + kq * 4],
                 Ab + (size_t)row * F_ + k0s + kq * 4);
        }
        {
            int kk = tid >> 3, j = tid & 7;
            cp16(&Bs[p * BPITCH + kk * BSTR + j * 4],
                 W1 + (size_t)(k0s + kk) * HID_ + j * 4);
        }
    };

#pragma unroll
    for (int s = 0; s < XS_ - 1; s++) {
        if (s < XNKT) stage(s, s);
        cp_commit();
    }

    for (int kt = 0; kt < XNKT; kt++) {
        const int p = kt & (XS_ - 1);
        if (kt + XS_ - 1 < XNKT) stage(kt + XS_ - 1, (kt + XS_ - 1) & (XS_ - 1));
        cp_commit();
        cp_wait<XS_ - 2>();
        __syncthreads();

        const float* Asp = &As[p * APITCH];
        const float* Bsp = &Bs[p * BPITCH];
#pragma unroll
        for (int kc = 0; kc < 4; kc++) {
            const int kb = kc * 8;
            float a0 = Asp[(w * 16 + g)     * ASTR + kb + t];
            float a1 = Asp[(w * 16 + g + 8) * ASTR + kb + t];
            float a2 = Asp[(w * 16 + g)     * ASTR + kb + t + 4];
            float a3 = Asp[(w * 16 + g + 8) * ASTR + kb + t + 4];
#pragma unroll
            for (int nt = 0; nt < 4; nt++) {
                float bb0 = Bsp[(kb + t)     * BSTR + nt * 8 + g];
                float bb1 = Bsp[(kb + t + 4) * BSTR + nt * 8 + g];
                mma_tf32(acc[nt], a0, a1, a2, a3, bb0, bb1);
            }
        }
        __syncthreads();
    }

    // Transposed bf16 store: g_XWt[(b*32 + col) * 2048 + node]
    const int gr = mb * BM + w * 16;
#pragma unroll
    for (int nt = 0; nt < 4; nt++) {
        const int c0 = nt * 8 + 2 * t;
        __nv_bfloat16* o0 = g_XWt + ((size_t)b * HID_ + c0) * N_;
        __nv_bfloat16* o1 = o0 + N_;
        o0[gr + g]     = __float2bfloat16_rn(acc[nt][0]);
        o1[gr + g]     = __float2bfloat16_rn(acc[nt][1]);
        o0[gr + g + 8] = __float2bfloat16_rn(acc[nt][2]);
        o1[gr + g + 8] = __float2bfloat16_rn(acc[nt][3]);
    }
}

// ---------------------------------------------------------------------------
// Kernel 2: Y = filtre @ XW per batch (M=2048,K=2048,N=32), bf16 mma,
// relu(Y+b1), deterministic column-sum -> g_part[b][mb][32].
// A: LDG fp32 -> cvt bf16 -> STS, 2-tile register pipeline, 2 smem stages.
// B: cp.async bf16 from g_XWt, 2 tiles ahead, 4 smem stages.
// grid (MB_, B_), 256 threads (8 warps x m16, 4 n8-tiles each).
// ---------------------------------------------------------------------------
__global__ __launch_bounds__(256) void main_kernel(const float* __restrict__ A,
                                                   const float* __restrict__ b1) {
    __shared__ __align__(16) __nv_bfloat16 As[2 * A_ELEMS];
    __shared__ __align__(16) __nv_bfloat16 Bs[4 * B_ELEMS];
    __shared__ float red[8 * HID_];

    const int tid = threadIdx.x;
    const int b = blockIdx.y;
    const int mb = blockIdx.x;
    const int w = tid >> 5;
    const int lane = tid & 31;
    const int g = lane >> 2;
    const int t = lane & 3;

    const float* Ab = A + ((size_t)b * N_ + (size_t)mb * BM) * N_;
    const __nv_bfloat16* Bb = g_XWt + (size_t)b * HID_ * N_;

    // A-load indices: 1024 16B-chunks per tile, 4 per thread
    const int arow = tid >> 3;            // rows handled: arow, arow+32, +64, +96
    const int akq = tid & 7;              // k-quad 0..7 (4 floats each)
    // B-load: 128 chunks, threads 0..127
    const int bn = tid >> 2;              // n row 0..31
    const int bq = tid & 3;               // k-oct 0..3 (8 bf16 each)

    float acc[4][4];
#pragma unroll
    for (int nt = 0; nt < 4; nt++)
#pragma unroll
        for (int i = 0; i < 4; i++) acc[nt][i] = 0.f;

    auto ldgA = [&](int kt, float4 (&r)[4]) {
        const int k0 = kt * BK;
#pragma unroll
        for (int i = 0; i < 4; i++)
            r[i] = *reinterpret_cast<const float4*>(
                Ab + (size_t)(arow + i * 32) * N_ + k0 + akq * 4);
    };
    auto cpB = [&](int kt) {
        if (tid < 128)
            cp16(&Bs[(kt & 3) * B_ELEMS + bn * MSTR + bq * 8],
                 Bb + (size_t)bn * N_ + kt * BK + bq * 8);
    };
    auto stsA = [&](int kt, float4 (&r)[4]) {
        __nv_bfloat16* dst = &As[(kt & 1) * A_ELEMS];
#pragma unroll
        for (int i = 0; i < 4; i++) {
            uint2 v;
            v.x = packbf(r[i].x, r[i].y);
            v.y = packbf(r[i].z, r[i].w);
            *reinterpret_cast<uint2*>(&dst[(arow + i * 32) * MSTR + akq * 4]) = v;
        }
    };

    float4 ra[4], rb[4];
    // prologue: A tiles 0,1 in regs; B tiles 0,1 via cp.async (one group each)
    ldgA(0, ra);
    ldgA(1, rb);
    cpB(0); cp_commit();
    cpB(1); cp_commit();

    auto step = [&](int kt, float4 (&r)[4]) {
        stsA(kt, r);
        if (kt + 2 < NKT) cpB(kt + 2);
        cp_commit();                       // uniform group accounting
        if (kt + 2 < NKT) ldgA(kt + 2, r); // WAR on regs: waits for STS reads
        cp_wait<2>();                      // B(kt) landed
        __syncthreads();                   // A STS + B visible to all

        const __nv_bfloat16* Asp = &As[(kt & 1) * A_ELEMS];
        const __nv_bfloat16* Bsp = &Bs[(kt & 3) * B_ELEMS];
#pragma unroll
        for (int kc = 0; kc < 2; kc++) {
            const int kb = kc * 16;
            uint32_t a0 = lds32(&Asp[(w * 16 + g)     * MSTR + kb + 2 * t]);
            uint32_t a1 = lds32(&Asp[(w * 16 + g + 8) * MSTR + kb + 2 * t]);
            uint32_t a2 = lds32(&Asp[(w * 16 + g)     * MSTR + kb + 2 * t + 8]);
            uint32_t a3 = lds32(&Asp[(w * 16 + g + 8) * MSTR + kb + 2 * t + 8]);
#pragma unroll
            for (int nt = 0; nt < 4; nt++) {
                uint32_t b0 = lds32(&Bsp[(nt * 8 + g) * MSTR + kb + 2 * t]);
                uint32_t b1 = lds32(&Bsp[(nt * 8 + g) * MSTR + kb + 2 * t + 8]);
                mma_bf16(acc[nt], a0, a1, a2, a3, b0, b1);
            }
        }
        // no trailing sync: next iter writes different A stage (kt+1)&1 and
        // B stage (kt+3)&3, both disjoint from any stage still being read.
    };

    for (int kt = 0; kt < NKT; kt += 2) {
        step(kt, ra);
        step(kt + 1, rb);
    }

    // Epilogue: +b1, relu, deterministic column-sum over this block's 128 rows.
    // Lane (g,t): rows w16+g, w16+g+8; cols nt*8+2t, +1.
    float2 csum[4];
#pragma unroll
    for (int nt = 0; nt < 4; nt++) {
        float2 bb = *reinterpret_cast<const float2*>(b1 + nt * 8 + 2 * t);
        float v0 = fmaxf(acc[nt][0] + bb.x, 0.f) + fmaxf(acc[nt][2] + bb.x, 0.f);
        float v1 = fmaxf(acc[nt][1] + bb.y, 0.f) + fmaxf(acc[nt][3] + bb.y, 0.f);
        csum[nt] = make_float2(v0, v1);
    }
#pragma unroll
    for (int nt = 0; nt < 4; nt++) {
#pragma unroll
        for (int off = 16; off >= 4; off >>= 1) {
            csum[nt].x += __shfl_xor_sync(0xffffffffu, csum[nt].x, off);
            csum[nt].y += __shfl_xor_sync(0xffffffffu, csum[nt].y, off);
        }
    }
    __syncthreads();   // all mma-phase smem reads done before red[] reuse pattern
    if (g == 0) {
#pragma unroll
        for (int nt = 0; nt < 4; nt++) {
            red[w * HID_ + nt * 8 + 2 * t + 0] = csum[nt].x;
            red[w * HID_ + nt * 8 + 2 * t + 1] = csum[nt].y;
        }
    }
    __syncthreads();
    if (tid < HID_) {
        float s = 0.f;
#pragma unroll
        for (int ww = 0; ww < 8; ww++) s += red[ww * HID_ + tid];
        g_part[((size_t)b * MB_ + mb) * HID_ + tid] = s;
    }
}

// ---------------------------------------------------------------------------
// Kernel 3: Xp = sum(partials); h = relu(Xp@Wd+bd); out = softmax(h@Wc+bc)
// ---------------------------------------------------------------------------
__global__ __launch_bounds__(512) void head_kernel(const float* __restrict__ Wd,
                                                   const float* __restrict__ bd,
                                                   const float* __restrict__ Wc,
                                                   const float* __restrict__ bc,
                                                   float* __restrict__ out) {
    __shared__ float xp[HID_];
    __shared__ float hbuf[FC_];
    __shared__ float logits[C_];
    const int b = blockIdx.x;
    const int tid = threadIdx.x;

    if (tid < HID_) {
        float s = 0.f;
#pragma unroll
        for (int mb = 0; mb < MB_; mb++)
            s += g_part[((size_t)b * MB_ + mb) * HID_ + tid];
        xp[tid] = s;
    }
    __syncthreads();

    {
        float acc = bd[tid];
#pragma unroll
        for (int h = 0; h < HID_; h++)
            acc = fmaf(xp[h], Wd[h * FC_ + tid], acc);
        hbuf[tid] = fmaxf(acc, 0.f);
    }
    __syncthreads();

    if (tid < C_) {
        float acc = bc[tid];
        for (int f = 0; f < FC_; f++)
            acc = fmaf(hbuf[f], Wc[f * C_ + tid], acc);
        logits[tid] = acc;
    }
    __syncthreads();

    if (tid == 0) {
        float mx = logits[0];
#pragma unroll
        for (int c = 1; c < C_; c++) mx = fmaxf(mx, logits[c]);
        float e[C_];
        float sum = 0.f;
#pragma unroll
        for (int c = 0; c < C_; c++) { e[c] = expf(logits[c] - mx); sum += e[c]; }
        float inv = 1.f / sum;
#pragma unroll
        for (int c = 0; c < C_; c++) out[b * C_ + c] = e[c] * inv;
    }
}

// ---------------------------------------------------------------------------
extern "C" void kernel_launch(void* const* d_in, const int* in_sizes, int n_in,
                              void* d_out, int out_size) {
    const float* filtre = (const float*)d_in[0];
    const float* X      = (const float*)d_in[1];
    // d_in[2] node_indicator: unused by the reference math
    const float* W1     = (const float*)d_in[3];
    const float* b1     = (const float*)d_in[4];
    // d_in[5] Ws: dead (softmax over size-1 cluster axis == 1)
    const float* Wd     = (const float*)d_in[6];
    const float* bd     = (const float*)d_in[7];
    const float* Wc     = (const float*)d_in[8];
    const float* bc     = (const float*)d_in[9];
    float* out = (float*)d_out;

    // Idempotent, non-stream host call (no allocation).
    cudaFuncSetAttribute(xw_kernel,
                         cudaFuncAttributeMaxDynamicSharedMemorySize, XW_SMEM);

    xw_kernel  <<<dim3(MB_, B_), 256, XW_SMEM>>>(X, W1);
    main_kernel<<<dim3(MB_, B_), 256>>>(filtre, b1);
    head_kernel<<<B_, FC_>>>(Wd, bd, Wc, bc, out);
}

// round 13
// speedup vs baseline: 1.3049x; 1.3049x over previous
#include <cuda_runtime.h>
#include <cstdint>

#define B_   16
#define N_   2048
#define F_   128
#define HID_ 32
#define FC_  512
#define C_   10

// ---- xw kernel (tf32 mma.sync, R8-proven) ----
#define XBM  128
#define BK   32
#define XMB  (N_ / XBM)    // 16
#define XS_  4
#define XNKT (F_ / BK)     // 4
#define ASTR 36
#define BSTR 40
#define XAPITCH (XBM * ASTR)
#define BPITCH  (BK * BSTR)
#define XW_SMEM ((XS_ * XAPITCH + XS_ * BPITCH) * 4)

// ---- main kernel (tf32 mma.sync, BM=256, single wave) ----
#define BM2  256
#define MB2  (N_ / BM2)    // 8
#define NKT  (N_ / BK)     // 64
#define S2   4
#define A2PITCH (BM2 * ASTR)
#define MAIN_SMEM ((S2 * A2PITCH + S2 * BPITCH) * 4)   // ~168 KB

// Scratch (no cudaMalloc allowed)
__device__ float g_XW[B_ * N_ * HID_];         // X @ W1  [B,N,32] fp32
__device__ float g_part[B_ * MB2 * HID_];      // per-block relu column sums

// ---------------- helpers ----------------
__device__ __forceinline__ void cp16(float* dst, const float* src) {
    unsigned s = (unsigned)__cvta_generic_to_shared(dst);
    asm volatile("cp.async.cg.shared.global [%0], [%1], 16;" :: "r"(s), "l"(src));
}
__device__ __forceinline__ void cp_commit() { asm volatile("cp.async.commit_group;"); }
template <int NN>
__device__ __forceinline__ void cp_wait() { asm volatile("cp.async.wait_group %0;" :: "n"(NN)); }

__device__ __forceinline__ void mma_tf32(float c[4], float a0, float a1, float a2, float a3,
                                         float b0, float b1) {
    asm volatile(
        "mma.sync.aligned.m16n8k8.row.col.f32.tf32.tf32.f32 "
        "{%0,%1,%2,%3}, {%4,%5,%6,%7}, {%8,%9}, {%0,%1,%2,%3};"
        : "+f"(c[0]), "+f"(c[1]), "+f"(c[2]), "+f"(c[3])
        : "r"(__float_as_uint(a0)), "r"(__float_as_uint(a1)),
          "r"(__float_as_uint(a2)), "r"(__float_as_uint(a3)),
          "r"(__float_as_uint(b0)), "r"(__float_as_uint(b1)));
}

// ---------------------------------------------------------------------------
// Kernel 1 (R8-proven): XW = X @ W1 -> g_XW [B,N,32] fp32.
// grid (XMB, B_), 256 threads.
// ---------------------------------------------------------------------------
__global__ __launch_bounds__(256) void xw_kernel(const float* __restrict__ Xg,
                                                 const float* __restrict__ W1) {
    extern __shared__ __align__(16) float smem[];
    float* As = smem;
    float* Bs = smem + XS_ * XAPITCH;

    const int tid = threadIdx.x;
    const int b = blockIdx.y;
    const int mb = blockIdx.x;
    const int w = tid >> 5;
    const int lane = tid & 31;
    const int g = lane >> 2;
    const int t = lane & 3;

    const float* Ab = Xg + ((size_t)b * N_ + (size_t)mb * XBM) * F_;

    float acc[4][4];
#pragma unroll
    for (int nt = 0; nt < 4; nt++)
#pragma unroll
        for (int i = 0; i < 4; i++) acc[nt][i] = 0.f;

    auto stage = [&](int kt, int p) {
        const int k0s = kt * BK;
#pragma unroll
        for (int i = 0; i < 4; i++) {
            int c = tid + i * 256;
            int row = c >> 3, kq = c & 7;
            cp16(&As[p * XAPITCH + row * ASTR + kq * 4],
                 Ab + (size_t)row * F_ + k0s + kq * 4);
        }
        {
            int kk = tid >> 3, j = tid & 7;
            cp16(&Bs[p * BPITCH + kk * BSTR + j * 4],
                 W1 + (size_t)(k0s + kk) * HID_ + j * 4);
        }
    };

#pragma unroll
    for (int s = 0; s < XS_ - 1; s++) {
        if (s < XNKT) stage(s, s);
        cp_commit();
    }

    for (int kt = 0; kt < XNKT; kt++) {
        const int p = kt & (XS_ - 1);
        if (kt + XS_ - 1 < XNKT) stage(kt + XS_ - 1, (kt + XS_ - 1) & (XS_ - 1));
        cp_commit();
        cp_wait<XS_ - 2>();
        __syncthreads();

        const float* Asp = &As[p * XAPITCH];
        const float* Bsp = &Bs[p * BPITCH];
#pragma unroll
        for (int kc = 0; kc < 4; kc++) {
            const int kb = kc * 8;
            float a0 = Asp[(w * 16 + g)     * ASTR + kb + t];
            float a1 = Asp[(w * 16 + g + 8) * ASTR + kb + t];
            float a2 = Asp[(w * 16 + g)     * ASTR + kb + t + 4];
            float a3 = Asp[(w * 16 + g + 8) * ASTR + kb + t + 4];
#pragma unroll
            for (int nt = 0; nt < 4; nt++) {
                float bb0 = Bsp[(kb + t)     * BSTR + nt * 8 + g];
                float bb1 = Bsp[(kb + t + 4) * BSTR + nt * 8 + g];
                mma_tf32(acc[nt], a0, a1, a2, a3, bb0, bb1);
            }
        }
        __syncthreads();
    }

    const size_t base = (size_t)b * N_ + (size_t)mb * XBM + w * 16;
#pragma unroll
    for (int nt = 0; nt < 4; nt++) {
        float2 v0 = make_float2(acc[nt][0], acc[nt][1]);
        float2 v1 = make_float2(acc[nt][2], acc[nt][3]);
        *reinterpret_cast<float2*>(&g_XW[(base + g)     * HID_ + nt * 8 + 2 * t]) = v0;
        *reinterpret_cast<float2*>(&g_XW[(base + g + 8) * HID_ + nt * 8 + 2 * t]) = v1;
    }
}

// ---------------------------------------------------------------------------
// Kernel 2: Y = filtre @ XW per batch (M=2048,K=2048,N=32), tf32 mma,
// relu(Y+b1), deterministic column-sum -> g_part[b][mb][32].
// BM=256: 8 warps of m32 x n32 (2 m16-frags x 4 n8-frags each);
// 4-stage cp.async pipeline (R8 skeleton). grid (MB2, B_) = 128 blocks.
// ---------------------------------------------------------------------------
__global__ __launch_bounds__(256) void main_kernel(const float* __restrict__ A,
                                                   const float* __restrict__ b1) {
    extern __shared__ __align__(16) float smem[];
    float* As = smem;                        // [S2][BM2*ASTR]
    float* Bs = smem + S2 * A2PITCH;         // [S2][BK*BSTR]
    __shared__ float red[8 * HID_];

    const int tid = threadIdx.x;
    const int b = blockIdx.y;
    const int mb = blockIdx.x;
    const int w = tid >> 5;
    const int lane = tid & 31;
    const int g = lane >> 2;
    const int t = lane & 3;

    const float* Ab = A + ((size_t)b * N_ + (size_t)mb * BM2) * N_;
    const float* Bb = g_XW + (size_t)b * N_ * HID_;

    float acc[2][4][4];
#pragma unroll
    for (int mf = 0; mf < 2; mf++)
#pragma unroll
        for (int nt = 0; nt < 4; nt++)
#pragma unroll
            for (int i = 0; i < 4; i++) acc[mf][nt][i] = 0.f;

    auto stage = [&](int kt, int p) {
        const int k0s = kt * BK;
#pragma unroll
        for (int i = 0; i < 8; i++) {                 // 2048 chunks, 8/thread
            int c = tid + i * 256;
            int row = c >> 3, kq = c & 7;
            cp16(&As[p * A2PITCH + row * ASTR + kq * 4],
                 Ab + (size_t)row * N_ + k0s + kq * 4);
        }
        {
            int kk = tid >> 3, j = tid & 7;
            cp16(&Bs[p * BPITCH + kk * BSTR + j * 4],
                 Bb + (size_t)(k0s + kk) * HID_ + j * 4);
        }
    };

#pragma unroll
    for (int s = 0; s < S2 - 1; s++) { stage(s, s); cp_commit(); }

    for (int kt = 0; kt < NKT; kt++) {
        const int p = kt & (S2 - 1);
        if (kt + S2 - 1 < NKT) stage(kt + S2 - 1, (kt + S2 - 1) & (S2 - 1));
        cp_commit();
        cp_wait<S2 - 2>();
        __syncthreads();

        const float* Asp = &As[p * A2PITCH];
        const float* Bsp = &Bs[p * BPITCH];
#pragma unroll
        for (int kc = 0; kc < 4; kc++) {
            const int kb = kc * 8;
            float bb0[4], bb1[4];
#pragma unroll
            for (int nt = 0; nt < 4; nt++) {
                bb0[nt] = Bsp[(kb + t)     * BSTR + nt * 8 + g];
                bb1[nt] = Bsp[(kb + t + 4) * BSTR + nt * 8 + g];
            }
#pragma unroll
            for (int mf = 0; mf < 2; mf++) {
                const int r0 = w * 32 + mf * 16 + g;
                float a0 = Asp[(r0)     * ASTR + kb + t];
                float a1 = Asp[(r0 + 8) * ASTR + kb + t];
                float a2 = Asp[(r0)     * ASTR + kb + t + 4];
                float a3 = Asp[(r0 + 8) * ASTR + kb + t + 4];
#pragma unroll
                for (int nt = 0; nt < 4; nt++)
                    mma_tf32(acc[mf][nt], a0, a1, a2, a3, bb0[nt], bb1[nt]);
            }
        }
        __syncthreads();
    }

    // Epilogue: +b1, relu, deterministic column-sum over this block's 256 rows.
    float2 csum[4];
#pragma unroll
    for (int nt = 0; nt < 4; nt++) {
        float2 bb = *reinterpret_cast<const float2*>(b1 + nt * 8 + 2 * t);
        float v0 = 0.f, v1 = 0.f;
#pragma unroll
        for (int mf = 0; mf < 2; mf++) {
            v0 += fmaxf(acc[mf][nt][0] + bb.x, 0.f) + fmaxf(acc[mf][nt][2] + bb.x, 0.f);
            v1 += fmaxf(acc[mf][nt][1] + bb.y, 0.f) + fmaxf(acc[mf][nt][3] + bb.y, 0.f);
        }
        csum[nt] = make_float2(v0, v1);
    }
#pragma unroll
    for (int nt = 0; nt < 4; nt++) {
#pragma unroll
        for (int off = 16; off >= 4; off >>= 1) {
            csum[nt].x += __shfl_xor_sync(0xffffffffu, csum[nt].x, off);
            csum[nt].y += __shfl_xor_sync(0xffffffffu, csum[nt].y, off);
        }
    }
    if (g == 0) {
#pragma unroll
        for (int nt = 0; nt < 4; nt++) {
            red[w * HID_ + nt * 8 + 2 * t + 0] = csum[nt].x;
            red[w * HID_ + nt * 8 + 2 * t + 1] = csum[nt].y;
        }
    }
    __syncthreads();
    if (tid < HID_) {
        float s = 0.f;
#pragma unroll
        for (int ww = 0; ww < 8; ww++) s += red[ww * HID_ + tid];
        g_part[((size_t)b * MB2 + mb) * HID_ + tid] = s;
    }
}

// ---------------------------------------------------------------------------
// Kernel 3: Xp = sum(partials); h = relu(Xp@Wd+bd); out = softmax(h@Wc+bc)
// ---------------------------------------------------------------------------
__global__ __launch_bounds__(512) void head_kernel(const float* __restrict__ Wd,
                                                   const float* __restrict__ bd,
                                                   const float* __restrict__ Wc,
                                                   const float* __restrict__ bc,
                                                   float* __restrict__ out) {
    __shared__ float xp[HID_];
    __shared__ float hbuf[FC_];
    __shared__ float logits[C_];
    const int b = blockIdx.x;
    const int tid = threadIdx.x;

    if (tid < HID_) {
        float s = 0.f;
#pragma unroll
        for (int mb = 0; mb < MB2; mb++)
            s += g_part[((size_t)b * MB2 + mb) * HID_ + tid];
        xp[tid] = s;
    }
    __syncthreads();

    {
        float acc = bd[tid];
#pragma unroll
        for (int h = 0; h < HID_; h++)
            acc = fmaf(xp[h], Wd[h * FC_ + tid], acc);
        hbuf[tid] = fmaxf(acc, 0.f);
    }
    __syncthreads();

    if (tid < C_) {
        float acc = bc[tid];
        for (int f = 0; f < FC_; f++)
            acc = fmaf(hbuf[f], Wc[f * C_ + tid], acc);
        logits[tid] = acc;
    }
    __syncthreads();

    if (tid == 0) {
        float mx = logits[0];
#pragma unroll
        for (int c = 1; c < C_; c++) mx = fmaxf(mx, logits[c]);
        float e[C_];
        float sum = 0.f;
#pragma unroll
        for (int c = 0; c < C_; c++) { e[c] = expf(logits[c] - mx); sum += e[c]; }
        float inv = 1.f / sum;
#pragma unroll
        for (int c = 0; c < C_; c++) out[b * C_ + c] = e[c] * inv;
    }
}

// ---------------------------------------------------------------------------
extern "C" void kernel_launch(void* const* d_in, const int* in_sizes, int n_in,
                              void* d_out, int out_size) {
    const float* filtre = (const float*)d_in[0];
    const float* X      = (const float*)d_in[1];
    // d_in[2] node_indicator: unused by the reference math
    const float* W1     = (const float*)d_in[3];
    const float* b1     = (const float*)d_in[4];
    // d_in[5] Ws: dead (softmax over size-1 cluster axis == 1)
    const float* Wd     = (const float*)d_in[6];
    const float* bd     = (const float*)d_in[7];
    const float* Wc     = (const float*)d_in[8];
    const float* bc     = (const float*)d_in[9];
    float* out = (float*)d_out;

    // Idempotent, non-stream host calls (no allocation).
    cudaFuncSetAttribute(xw_kernel,
                         cudaFuncAttributeMaxDynamicSharedMemorySize, XW_SMEM);
    cudaFuncSetAttribute(main_kernel,
                         cudaFuncAttributeMaxDynamicSharedMemorySize, MAIN_SMEM);

    xw_kernel  <<<dim3(XMB, B_), 256, XW_SMEM  >>>(X, W1);
    main_kernel<<<dim3(MB2, B_), 256, MAIN_SMEM>>>(filtre, b1);
    head_kernel<<<B_, FC_>>>(Wd, bd, Wc, bc, out);
}

// round 14
// speedup vs baseline: 1.3090x; 1.0032x over previous
#include <cuda_runtime.h>
#include <cstdint>

#define B_   16
#define N_   2048
#define F_   128
#define HID_ 32
#define FC_  512
#define C_   10

// ---- xw kernel (tf32 mma.sync) ----
#define XBM  128
#define BK   32
#define XMB  (N_ / XBM)    // 16
#define XS_  3
#define XNKT (F_ / BK)     // 4
#define ASTR 36
#define BSTR 40
#define XAPITCH (XBM * ASTR)
#define BPITCH  (BK * BSTR)
#define XW_SMEM ((XS_ * XAPITCH + XS_ * BPITCH) * 4)     // ~70 KB -> 3 blocks/SM

// ---- main kernel (tf32 mma.sync, BM=256, single wave, 5-stage) ----
#define BM2  256
#define MB2  (N_ / BM2)    // 8
#define NKT  (N_ / BK)     // 64
#define S2   5
#define A2PITCH (BM2 * ASTR)
#define MAIN_SMEM ((S2 * A2PITCH + S2 * BPITCH) * 4)     // ~210 KB

// Scratch (no cudaMalloc allowed)
__device__ float g_XW[B_ * N_ * HID_];         // X @ W1  [B,N,32] fp32
__device__ float g_part[B_ * MB2 * HID_];      // per-block relu column sums

// ---------------- helpers ----------------
__device__ __forceinline__ void cp16(float* dst, const float* src) {
    unsigned s = (unsigned)__cvta_generic_to_shared(dst);
    asm volatile("cp.async.cg.shared.global [%0], [%1], 16;" :: "r"(s), "l"(src));
}
__device__ __forceinline__ void cp_commit() { asm volatile("cp.async.commit_group;"); }
template <int NN>
__device__ __forceinline__ void cp_wait() { asm volatile("cp.async.wait_group %0;" :: "n"(NN)); }

__device__ __forceinline__ void mma_tf32(float c[4], float a0, float a1, float a2, float a3,
                                         float b0, float b1) {
    asm volatile(
        "mma.sync.aligned.m16n8k8.row.col.f32.tf32.tf32.f32 "
        "{%0,%1,%2,%3}, {%4,%5,%6,%7}, {%8,%9}, {%0,%1,%2,%3};"
        : "+f"(c[0]), "+f"(c[1]), "+f"(c[2]), "+f"(c[3])
        : "r"(__float_as_uint(a0)), "r"(__float_as_uint(a1)),
          "r"(__float_as_uint(a2)), "r"(__float_as_uint(a3)),
          "r"(__float_as_uint(b0)), "r"(__float_as_uint(b1)));
}

// ---------------------------------------------------------------------------
// Kernel 1: XW = X @ W1 -> g_XW [B,N,32] fp32.
// Single-sync 3-stage pipeline. grid (XMB, B_), 256 threads.
// ---------------------------------------------------------------------------
__global__ __launch_bounds__(256) void xw_kernel(const float* __restrict__ Xg,
                                                 const float* __restrict__ W1) {
    extern __shared__ __align__(16) float smem[];
    float* As = smem;
    float* Bs = smem + XS_ * XAPITCH;

    const int tid = threadIdx.x;
    const int b = blockIdx.y;
    const int mb = blockIdx.x;
    const int w = tid >> 5;
    const int lane = tid & 31;
    const int g = lane >> 2;
    const int t = lane & 3;

    const float* Ab = Xg + ((size_t)b * N_ + (size_t)mb * XBM) * F_;

    float acc[4][4];
#pragma unroll
    for (int nt = 0; nt < 4; nt++)
#pragma unroll
        for (int i = 0; i < 4; i++) acc[nt][i] = 0.f;

    auto stage = [&](int kt, int p) {
        const int k0s = kt * BK;
#pragma unroll
        for (int i = 0; i < 4; i++) {
            int c = tid + i * 256;
            int row = c >> 3, kq = c & 7;
            cp16(&As[p * XAPITCH + row * ASTR + kq * 4],
                 Ab + (size_t)row * F_ + k0s + kq * 4);
        }
        {
            int kk = tid >> 3, j = tid & 7;
            cp16(&Bs[p * BPITCH + kk * BSTR + j * 4],
                 W1 + (size_t)(k0s + kk) * HID_ + j * 4);
        }
    };

#pragma unroll
    for (int s = 0; s < XS_ - 1; s++) { stage(s, s); cp_commit(); }

#pragma unroll
    for (int kt = 0; kt < XNKT; kt++) {
        cp_wait<XS_ - 2>();
        __syncthreads();
        if (kt + XS_ - 1 < XNKT) stage(kt + XS_ - 1, (kt + XS_ - 1) % XS_);
        cp_commit();

        const int p = kt % XS_;
        const float* Asp = &As[p * XAPITCH];
        const float* Bsp = &Bs[p * BPITCH];
#pragma unroll
        for (int kc = 0; kc < 4; kc++) {
            const int kb = kc * 8;
            float a0 = Asp[(w * 16 + g)     * ASTR + kb + t];
            float a1 = Asp[(w * 16 + g + 8) * ASTR + kb + t];
            float a2 = Asp[(w * 16 + g)     * ASTR + kb + t + 4];
            float a3 = Asp[(w * 16 + g + 8) * ASTR + kb + t + 4];
#pragma unroll
            for (int nt = 0; nt < 4; nt++) {
                float bb0 = Bsp[(kb + t)     * BSTR + nt * 8 + g];
                float bb1 = Bsp[(kb + t + 4) * BSTR + nt * 8 + g];
                mma_tf32(acc[nt], a0, a1, a2, a3, bb0, bb1);
            }
        }
    }

    const size_t base = (size_t)b * N_ + (size_t)mb * XBM + w * 16;
#pragma unroll
    for (int nt = 0; nt < 4; nt++) {
        float2 v0 = make_float2(acc[nt][0], acc[nt][1]);
        float2 v1 = make_float2(acc[nt][2], acc[nt][3]);
        *reinterpret_cast<float2*>(&g_XW[(base + g)     * HID_ + nt * 8 + 2 * t]) = v0;
        *reinterpret_cast<float2*>(&g_XW[(base + g + 8) * HID_ + nt * 8 + 2 * t]) = v1;
    }
}

// ---------------------------------------------------------------------------
// Kernel 2: Y = filtre @ XW per batch (M=2048,K=2048,N=32), tf32 mma,
// relu(Y+b1), deterministic column-sum -> g_part[b][mb][32].
// BM=256, 8 warps of m32 x n32; 5-stage single-sync cp.async pipeline.
// grid (MB2, B_) = 128 blocks (one balanced wave).
// ---------------------------------------------------------------------------
__global__ __launch_bounds__(256) void main_kernel(const float* __restrict__ A,
                                                   const float* __restrict__ b1) {
    extern __shared__ __align__(16) float smem[];
    float* As = smem;                        // [S2][BM2*ASTR]
    float* Bs = smem + S2 * A2PITCH;         // [S2][BK*BSTR]
    __shared__ float red[8 * HID_];

    const int tid = threadIdx.x;
    const int b = blockIdx.y;
    const int mb = blockIdx.x;
    const int w = tid >> 5;
    const int lane = tid & 31;
    const int g = lane >> 2;
    const int t = lane & 3;

    const float* Ab = A + ((size_t)b * N_ + (size_t)mb * BM2) * N_;
    const float* Bb = g_XW + (size_t)b * N_ * HID_;

    float acc[2][4][4];
#pragma unroll
    for (int mf = 0; mf < 2; mf++)
#pragma unroll
        for (int nt = 0; nt < 4; nt++)
#pragma unroll
            for (int i = 0; i < 4; i++) acc[mf][nt][i] = 0.f;

    auto stage = [&](int kt, int p) {
        const int k0s = kt * BK;
#pragma unroll
        for (int i = 0; i < 8; i++) {                 // 2048 chunks, 8/thread
            int c = tid + i * 256;
            int row = c >> 3, kq = c & 7;
            cp16(&As[p * A2PITCH + row * ASTR + kq * 4],
                 Ab + (size_t)row * N_ + k0s + kq * 4);
        }
        {
            int kk = tid >> 3, j = tid & 7;
            cp16(&Bs[p * BPITCH + kk * BSTR + j * 4],
                 Bb + (size_t)(k0s + kk) * HID_ + j * 4);
        }
    };

#pragma unroll
    for (int s = 0; s < S2 - 1; s++) { stage(s, s); cp_commit(); }

    for (int kt = 0; kt < NKT; kt++) {
        cp_wait<S2 - 2>();          // tile kt landed
        __syncthreads();            // all reads of buffer (kt-1)%S2 are done
        if (kt + S2 - 1 < NKT) stage(kt + S2 - 1, (kt + S2 - 1) % S2);
        cp_commit();                // uniform group accounting (maybe empty)

        const int p = kt % S2;
        const float* Asp = &As[p * A2PITCH];
        const float* Bsp = &Bs[p * BPITCH];
#pragma unroll
        for (int kc = 0; kc < 4; kc++) {
            const int kb = kc * 8;
            float bb0[4], bb1[4];
#pragma unroll
            for (int nt = 0; nt < 4; nt++) {
                bb0[nt] = Bsp[(kb + t)     * BSTR + nt * 8 + g];
                bb1[nt] = Bsp[(kb + t + 4) * BSTR + nt * 8 + g];
            }
#pragma unroll
            for (int mf = 0; mf < 2; mf++) {
                const int r0 = w * 32 + mf * 16 + g;
                float a0 = Asp[(r0)     * ASTR + kb + t];
                float a1 = Asp[(r0 + 8) * ASTR + kb + t];
                float a2 = Asp[(r0)     * ASTR + kb + t + 4];
                float a3 = Asp[(r0 + 8) * ASTR + kb + t + 4];
#pragma unroll
                for (int nt = 0; nt < 4; nt++)
                    mma_tf32(acc[mf][nt], a0, a1, a2, a3, bb0[nt], bb1[nt]);
            }
        }
    }

    // Epilogue: +b1, relu, deterministic column-sum over this block's 256 rows.
    float2 csum[4];
#pragma unroll
    for (int nt = 0; nt < 4; nt++) {
        float2 bb = *reinterpret_cast<const float2*>(b1 + nt * 8 + 2 * t);
        float v0 = 0.f, v1 = 0.f;
#pragma unroll
        for (int mf = 0; mf < 2; mf++) {
            v0 += fmaxf(acc[mf][nt][0] + bb.x, 0.f) + fmaxf(acc[mf][nt][2] + bb.x, 0.f);
            v1 += fmaxf(acc[mf][nt][1] + bb.y, 0.f) + fmaxf(acc[mf][nt][3] + bb.y, 0.f);
        }
        csum[nt] = make_float2(v0, v1);
    }
#pragma unroll
    for (int nt = 0; nt < 4; nt++) {
#pragma unroll
        for (int off = 16; off >= 4; off >>= 1) {
            csum[nt].x += __shfl_xor_sync(0xffffffffu, csum[nt].x, off);
            csum[nt].y += __shfl_xor_sync(0xffffffffu, csum[nt].y, off);
        }
    }
    __syncthreads();
    if (g == 0) {
#pragma unroll
        for (int nt = 0; nt < 4; nt++) {
            red[w * HID_ + nt * 8 + 2 * t + 0] = csum[nt].x;
            red[w * HID_ + nt * 8 + 2 * t + 1] = csum[nt].y;
        }
    }
    __syncthreads();
    if (tid < HID_) {
        float s = 0.f;
#pragma unroll
        for (int ww = 0; ww < 8; ww++) s += red[ww * HID_ + tid];
        g_part[((size_t)b * MB2 + mb) * HID_ + tid] = s;
    }
}

// ---------------------------------------------------------------------------
// Kernel 3: Xp = sum(partials); h = relu(Xp@Wd+bd); out = softmax(h@Wc+bc)
// ---------------------------------------------------------------------------
__global__ __launch_bounds__(512) void head_kernel(const float* __restrict__ Wd,
                                                   const float* __restrict__ bd,
                                                   const float* __restrict__ Wc,
                                                   const float* __restrict__ bc,
                                                   float* __restrict__ out) {
    __shared__ float xp[HID_];
    __shared__ float hbuf[FC_];
    __shared__ float logits[C_];
    const int b = blockIdx.x;
    const int tid = threadIdx.x;

    if (tid < HID_) {
        float s = 0.f;
#pragma unroll
        for (int mb = 0; mb < MB2; mb++)
            s += g_part[((size_t)b * MB2 + mb) * HID_ + tid];
        xp[tid] = s;
    }
    __syncthreads();

    {
        float acc = bd[tid];
#pragma unroll
        for (int h = 0; h < HID_; h++)
            acc = fmaf(xp[h], Wd[h * FC_ + tid], acc);
        hbuf[tid] = fmaxf(acc, 0.f);
    }
    __syncthreads();

    if (tid < C_) {
        float acc = bc[tid];
        for (int f = 0; f < FC_; f++)
            acc = fmaf(hbuf[f], Wc[f * C_ + tid], acc);
        logits[tid] = acc;
    }
    __syncthreads();

    if (tid == 0) {
        float mx = logits[0];
#pragma unroll
        for (int c = 1; c < C_; c++) mx = fmaxf(mx, logits[c]);
        float e[C_];
        float sum = 0.f;
#pragma unroll
        for (int c = 0; c < C_; c++) { e[c] = expf(logits[c] - mx); sum += e[c]; }
        float inv = 1.f / sum;
#pragma unroll
        for (int c = 0; c < C_; c++) out[b * C_ + c] = e[c] * inv;
    }
}

// ---------------------------------------------------------------------------
extern "C" void kernel_launch(void* const* d_in, const int* in_sizes, int n_in,
                              void* d_out, int out_size) {
    const float* filtre = (const float*)d_in[0];
    const float* X      = (const float*)d_in[1];
    // d_in[2] node_indicator: unused by the reference math
    const float* W1     = (const float*)d_in[3];
    const float* b1     = (const float*)d_in[4];
    // d_in[5] Ws: dead (softmax over size-1 cluster axis == 1)
    const float* Wd     = (const float*)d_in[6];
    const float* bd     = (const float*)d_in[7];
    const float* Wc     = (const float*)d_in[8];
    const float* bc     = (const float*)d_in[9];
    float* out = (float*)d_out;

    // Idempotent, non-stream host calls (no allocation).
    cudaFuncSetAttribute(xw_kernel,
                         cudaFuncAttributeMaxDynamicSharedMemorySize, XW_SMEM);
    cudaFuncSetAttribute(main_kernel,
                         cudaFuncAttributeMaxDynamicSharedMemorySize, MAIN_SMEM);

    xw_kernel  <<<dim3(XMB, B_), 256, XW_SMEM  >>>(X, W1);
    main_kernel<<<dim3(MB2, B_), 256, MAIN_SMEM>>>(filtre, b1);
    head_kernel<<<B_, FC_>>>(Wd, bd, Wc, bc, out);
}